// round 16
// baseline (speedup 1.0000x reference)
#include <cuda_runtime.h>
#include <cuda_fp16.h>

#define CC   128
#define PCH  6
#define SS   131072
#define NTOK 262144
#define TOK  64
#define NTHREADS 256
#define NHEAD 8

#define STRA 68      // fp16 activation row stride (u32 words)
#define ASTR 68      // fp32 residual A column stride: A[c][t]

// ---- shared memory layout (32-bit word offsets) ----
#define OFF_A    0                       // fp32 A [128][68] col-major
#define OFF_X    (128*ASTR)              // 8704
#define OFF_Q    (OFF_X + 64*STRA)       // 13056
#define OFF_K    (OFF_Q + 64*STRA)       // 17408
#define OFF_V    (OFF_K + 64*STRA)       // 21760
#define OFF_X2A  OFF_Q                   // FFN relu buf A (Q dead in FFN)
#define OFF_X2B  OFF_K                   // FFN relu buf B (K dead in FFN)
#define OFF_POL  (OFF_V + 64*STRA)       // 26112
#define OFF_RED  (OFF_POL + PCH*64)      // 26496: LN reduction scratch
#define SMEM_WORDS (OFF_RED + 512)       // 27008
#define SMEM_BYTES (SMEM_WORDS*4)        // 108032 B -> 2 CTAs/SM

// 12 fragment blocks of 128x128: Wq,Wk,Wv,Wo, W1 n-chunks x4, W2 k-chunks x4
__device__ unsigned g_wfrag[12 * 8192];

// ---- fp16 helpers ----
__device__ __forceinline__ unsigned pk(float lo, float hi) {
    __half2 h = __floats2half2_rn(lo, hi);
    return *reinterpret_cast<unsigned*>(&h);
}
__device__ __forceinline__ float2 up(unsigned w) {
    __half2 h = *reinterpret_cast<__half2*>(&w);
    return __half22float2(h);
}
__device__ __forceinline__ void up8(float* f, uint4 u) {
    float2 a = up(u.x), b = up(u.y), c = up(u.z), d = up(u.w);
    f[0] = a.x; f[1] = a.y; f[2] = b.x; f[3] = b.y;
    f[4] = c.x; f[5] = c.y; f[6] = d.x; f[7] = d.y;
}
__device__ __forceinline__ void mma16(float (&d)[4],
    unsigned a0, unsigned a1, unsigned a2, unsigned a3, unsigned b0, unsigned b1)
{
    asm("mma.sync.aligned.m16n8k16.row.col.f32.f16.f16.f32 "
        "{%0,%1,%2,%3}, {%4,%5,%6,%7}, {%8,%9}, {%0,%1,%2,%3};"
        : "+f"(d[0]), "+f"(d[1]), "+f"(d[2]), "+f"(d[3])
        : "r"(a0), "r"(a1), "r"(a2), "r"(a3), "r"(b0), "r"(b1));
}
__device__ __forceinline__ void ldsm4(unsigned (&a)[4], unsigned addr) {
    asm volatile("ldmatrix.sync.aligned.m8n8.x4.shared.b16 {%0,%1,%2,%3}, [%4];"
        : "=r"(a[0]), "=r"(a[1]), "=r"(a[2]), "=r"(a[3]) : "r"(addr));
}

// ---- weight conversion kernel: fp32 row-major -> fp16 fragment-major ----
__global__ void convert_weights(const float* __restrict__ Wq, const float* __restrict__ Wk,
                                const float* __restrict__ Wv, const float* __restrict__ Wo,
                                const float* __restrict__ W1, const float* __restrict__ W2)
{
    int gid = blockIdx.x * blockDim.x + threadIdx.x;
    int blk = gid >> 13;
    int w   = gid & 8191;
    int q4   = w & 3;
    int lane = (w >> 2) & 31;
    int h    = (w >> 7) & 1;
    int nw   = (w >> 8) & 3;
    int ks   = w >> 10;
    int j    = q4 & 1;
    int nt   = h * 2 + (q4 >> 1);
    int qd = lane >> 2, tg = lane & 3;
    int k = ks * 16 + tg * 2 + j * 8;
    int n = nw * 32 + nt * 8 + qd;

    const float* W; int ld = 128, k0 = 0, n0 = 0;
    if      (blk == 0) W = Wq;
    else if (blk == 1) W = Wk;
    else if (blk == 2) W = Wv;
    else if (blk == 3) W = Wo;
    else if (blk < 8)  { W = W1; ld = 512; n0 = (blk - 4) * 128; }
    else               { W = W2; k0 = (blk - 8) * 128; }

    const float* p = W + (size_t)(k0 + k) * ld + n0 + n;
    g_wfrag[gid] = pk(p[0], p[ld]);
}

// ---- single GEMM (R11-proven): acc[2][4][4], A+B pipelined 1-ahead ----
__device__ __forceinline__ void gemm_f(
    const unsigned* __restrict__ Wf, const unsigned* __restrict__ Xs,
    float (&acc)[2][4][4], int tid)
{
    const int lane = tid & 31, wid = tid >> 5;
    const int mw = wid & 1, nw = wid >> 1;

    unsigned abase;
    {
        const unsigned* p = Xs + (mw * 32 + (lane & 15)) * STRA;
        abase = (unsigned)__cvta_generic_to_shared(p) + ((lane >> 4) << 4);
    }
    const uint4* bp = (const uint4*)Wf + nw * 64 + lane;

    unsigned aC[2][4], aN[2][4];
    uint4 b0C, b1C, b0N, b1N;
    ldsm4(aC[0], abase);
    ldsm4(aC[1], abase + 16 * STRA * 4);
    b0C = bp[0]; b1C = bp[32];

    #pragma unroll
    for (int ks = 0; ks < 8; ++ks) {
        if (ks < 7) {
            unsigned an = abase + (ks + 1) * 32;
            ldsm4(aN[0], an);
            ldsm4(aN[1], an + 16 * STRA * 4);
            b0N = bp[(ks + 1) * 256];
            b1N = bp[(ks + 1) * 256 + 32];
        }
        #pragma unroll
        for (int mm = 0; mm < 2; ++mm) {
            mma16(acc[mm][0], aC[mm][0], aC[mm][1], aC[mm][2], aC[mm][3], b0C.x, b0C.y);
            mma16(acc[mm][1], aC[mm][0], aC[mm][1], aC[mm][2], aC[mm][3], b0C.z, b0C.w);
            mma16(acc[mm][2], aC[mm][0], aC[mm][1], aC[mm][2], aC[mm][3], b1C.x, b1C.y);
            mma16(acc[mm][3], aC[mm][0], aC[mm][1], aC[mm][2], aC[mm][3], b1C.z, b1C.w);
        }
        #pragma unroll
        for (int mm = 0; mm < 2; ++mm)
            #pragma unroll
            for (int r = 0; r < 4; ++r) aC[mm][r] = aN[mm][r];
        b0C = b0N; b1C = b1N;
    }
}

// ---- fused dual-B GEMM with PIPELINED A: one A pass feeds two weight blocks ----
__device__ __forceinline__ void gemm2(
    const unsigned* __restrict__ W0, const unsigned* __restrict__ W1w,
    const unsigned* __restrict__ Xs,
    float (&acc)[2][8][4], int tid)
{
    const int lane = tid & 31, wid = tid >> 5;
    const int mw = wid & 1, nw = wid >> 1;

    unsigned abase;
    {
        const unsigned* p = Xs + (mw * 32 + (lane & 15)) * STRA;
        abase = (unsigned)__cvta_generic_to_shared(p) + ((lane >> 4) << 4);
    }
    const uint4* bq = (const uint4*)W0  + nw * 64 + lane;
    const uint4* bk = (const uint4*)W1w + nw * 64 + lane;

    unsigned aC[2][4], aN[2][4];
    uint4 q0, q1, k0, k1;
    ldsm4(aC[0], abase);
    ldsm4(aC[1], abase + 16 * STRA * 4);
    q0 = bq[0]; q1 = bq[32]; k0 = bk[0]; k1 = bk[32];

    #pragma unroll
    for (int ks = 0; ks < 8; ++ks) {
        uint4 nq0 = q0, nq1 = q1, nk0 = k0, nk1 = k1;
        if (ks < 7) {
            unsigned an = abase + (ks + 1) * 32;
            ldsm4(aN[0], an);
            ldsm4(aN[1], an + 16 * STRA * 4);
            nq0 = bq[(ks + 1) * 256]; nq1 = bq[(ks + 1) * 256 + 32];
            nk0 = bk[(ks + 1) * 256]; nk1 = bk[(ks + 1) * 256 + 32];
        }
        #pragma unroll
        for (int mm = 0; mm < 2; ++mm) {
            mma16(acc[mm][0], aC[mm][0], aC[mm][1], aC[mm][2], aC[mm][3], q0.x, q0.y);
            mma16(acc[mm][1], aC[mm][0], aC[mm][1], aC[mm][2], aC[mm][3], q0.z, q0.w);
            mma16(acc[mm][2], aC[mm][0], aC[mm][1], aC[mm][2], aC[mm][3], q1.x, q1.y);
            mma16(acc[mm][3], aC[mm][0], aC[mm][1], aC[mm][2], aC[mm][3], q1.z, q1.w);
            mma16(acc[mm][4], aC[mm][0], aC[mm][1], aC[mm][2], aC[mm][3], k0.x, k0.y);
            mma16(acc[mm][5], aC[mm][0], aC[mm][1], aC[mm][2], aC[mm][3], k0.z, k0.w);
            mma16(acc[mm][6], aC[mm][0], aC[mm][1], aC[mm][2], aC[mm][3], k1.x, k1.y);
            mma16(acc[mm][7], aC[mm][0], aC[mm][1], aC[mm][2], aC[mm][3], k1.z, k1.w);
        }
        #pragma unroll
        for (int mm = 0; mm < 2; ++mm)
            #pragma unroll
            for (int r = 0; r < 4; ++r) aC[mm][r] = aN[mm][r];
        q0 = nq0; q1 = nq1; k0 = nk0; k1 = nk1;
    }
}

// epilogue (wide acc, nt base 0 or 4) -> fp16 buffer, +bias, optional relu
__device__ __forceinline__ void epi16w(float (&acc)[2][8][4], int base,
                                       unsigned* __restrict__ dst,
                                       const float* __restrict__ bias, bool relu, int tid)
{
    const int lane = tid & 31, wid = tid >> 5;
    const int mw = wid & 1, nw = wid >> 1;
    const int qd = lane >> 2, tg = lane & 3;
    #pragma unroll
    for (int nt = 0; nt < 4; ++nt) {
        const int cb = nw * 32 + nt * 8 + tg * 2;
        float2 b = *(const float2*)(bias + cb);
        #pragma unroll
        for (int mm = 0; mm < 2; ++mm) {
            const int r0 = mw * 32 + mm * 16 + qd;
            float v0 = acc[mm][base + nt][0] + b.x, v1 = acc[mm][base + nt][1] + b.y;
            float v2 = acc[mm][base + nt][2] + b.x, v3 = acc[mm][base + nt][3] + b.y;
            if (relu) {
                v0 = fmaxf(v0, 0.f); v1 = fmaxf(v1, 0.f);
                v2 = fmaxf(v2, 0.f); v3 = fmaxf(v3, 0.f);
            }
            dst[r0 * STRA + (cb >> 1)]       = pk(v0, v1);
            dst[(r0 + 8) * STRA + (cb >> 1)] = pk(v2, v3);
        }
    }
}

// epilogue (narrow acc) -> fp16 buffer
__device__ __forceinline__ void epi16n(float (&acc)[2][4][4], unsigned* __restrict__ dst,
                                       const float* __restrict__ bias, int tid)
{
    const int lane = tid & 31, wid = tid >> 5;
    const int mw = wid & 1, nw = wid >> 1;
    const int qd = lane >> 2, tg = lane & 3;
    #pragma unroll
    for (int nt = 0; nt < 4; ++nt) {
        const int cb = nw * 32 + nt * 8 + tg * 2;
        float2 b = *(const float2*)(bias + cb);
        #pragma unroll
        for (int mm = 0; mm < 2; ++mm) {
            const int r0 = mw * 32 + mm * 16 + qd;
            dst[r0 * STRA + (cb >> 1)]       = pk(acc[mm][nt][0] + b.x, acc[mm][nt][1] + b.y);
            dst[(r0 + 8) * STRA + (cb >> 1)] = pk(acc[mm][nt][2] + b.x, acc[mm][nt][3] + b.y);
        }
    }
}

// epilogue -> fp32 A (col-major) RMW: A[c][t] += acc (+bias if non-null)
__device__ __forceinline__ void epi32A(float (&acc)[2][4][4], float* __restrict__ A,
                                       const float* __restrict__ bias, int tid)
{
    const int lane = tid & 31, wid = tid >> 5;
    const int mw = wid & 1, nw = wid >> 1;
    const int qd = lane >> 2, tg = lane & 3;
    #pragma unroll
    for (int nt = 0; nt < 4; ++nt) {
        const int cb = nw * 32 + nt * 8 + tg * 2;
        float bx = 0.f, by = 0.f;
        if (bias) { float2 b = *(const float2*)(bias + cb); bx = b.x; by = b.y; }
        #pragma unroll
        for (int mm = 0; mm < 2; ++mm) {
            const int r0 = mw * 32 + mm * 16 + qd;
            A[cb * ASTR + r0]           += acc[mm][nt][0] + bx;
            A[(cb + 1) * ASTR + r0]     += acc[mm][nt][1] + by;
            A[cb * ASTR + r0 + 8]       += acc[mm][nt][2] + bx;
            A[(cb + 1) * ASTR + r0 + 8] += acc[mm][nt][3] + by;
        }
    }
}

// LayerNorm: conflict-free mapping t=tid&63, q=tid>>6; smem 2-stage reduce.
__device__ __forceinline__ void lnA(const float* __restrict__ A, unsigned* __restrict__ X,
                                    const float* __restrict__ g, const float* __restrict__ be,
                                    float* __restrict__ red, int tid)
{
    const int t = tid & 63, q = tid >> 6;
    const float* Ac = A + q * 32 * ASTR + t;
    float v[32];
    float s = 0.f, sq = 0.f;
    #pragma unroll
    for (int i = 0; i < 32; ++i) {
        v[i] = Ac[i * ASTR];
        s += v[i]; sq += v[i] * v[i];
    }
    red[q * 64 + t]       = s;
    red[256 + q * 64 + t] = sq;
    __syncthreads();
    float S = 0.f, SQ = 0.f;
    #pragma unroll
    for (int k = 0; k < 4; ++k) {
        S  += red[k * 64 + t];
        SQ += red[256 + k * 64 + t];
    }
    float m = S * (1.f / CC);
    float rs = rsqrtf(SQ * (1.f / CC) - m * m + 1e-5f);

    const float2* g2 = (const float2*)(g + q * 32);
    const float2* b2 = (const float2*)(be + q * 32);
    uint4* o = (uint4*)(X + t * STRA + q * 16);
    #pragma unroll
    for (int c4 = 0; c4 < 4; ++c4) {
        uint4 w;
        unsigned r[4];
        #pragma unroll
        for (int k = 0; k < 4; ++k) {
            int i = c4 * 4 + k;
            float2 gg = g2[i], bb = b2[i];
            r[k] = pk((v[2*i] - m) * rs * gg.x + bb.x,
                      (v[2*i+1] - m) * rs * gg.y + bb.y);
        }
        w.x = r[0]; w.y = r[1]; w.z = r[2]; w.w = r[3];
        o[c4] = w;
    }
}

#define ZACC(a)  { _Pragma("unroll") for (int _m = 0; _m < 2; ++_m) _Pragma("unroll") for (int _n = 0; _n < 4; ++_n) { a[_m][_n][0]=0.f; a[_m][_n][1]=0.f; a[_m][_n][2]=0.f; a[_m][_n][3]=0.f; } }
#define ZACC8(a) { _Pragma("unroll") for (int _m = 0; _m < 2; ++_m) _Pragma("unroll") for (int _n = 0; _n < 8; ++_n) { a[_m][_n][0]=0.f; a[_m][_n][1]=0.f; a[_m][_n][2]=0.f; a[_m][_n][3]=0.f; } }

__global__ void __launch_bounds__(NTHREADS, 2)
polar_attention_kernel(
    const float* __restrict__ x,   const float* __restrict__ polar,
    const float* __restrict__ bq,  const float* __restrict__ bk,
    const float* __restrict__ bv,  const float* __restrict__ Wp,
    const float* __restrict__ bpv, const float* __restrict__ bo,
    const float* __restrict__ g1,  const float* __restrict__ be1,
    const float* __restrict__ g2,  const float* __restrict__ be2,
    const float* __restrict__ bf1, const float* __restrict__ bf2,
    float* __restrict__ out)
{
    extern __shared__ float sm[];
    unsigned* smu = (unsigned*)sm;
    float*    A   = sm + OFF_A;
    unsigned* X16 = smu + OFF_X;
    unsigned* Q16 = smu + OFF_Q;
    unsigned* K16 = smu + OFF_K;
    unsigned* V16 = smu + OFF_V;
    unsigned* X2A = smu + OFF_X2A;
    unsigned* X2B = smu + OFF_X2B;
    float*    pol = sm + OFF_POL;
    float*    red = sm + OFF_RED;

    const int tid = threadIdx.x;
    const int n0  = blockIdx.x * TOK;
    const int b   = n0 / SS;
    const int s0  = n0 % SS;

    const float* xg = x + (size_t)(b * CC) * SS + s0;
    const float* pg = polar + (size_t)(b * PCH) * SS + s0;

    // ---- load x tile (col-major A) + polar ----
    #pragma unroll
    for (int idx = tid; idx < 2048; idx += NTHREADS) {
        int c = idx >> 4, t4 = (idx & 15) * 4;
        *(float4*)(A + c * ASTR + t4) = *(const float4*)(xg + (size_t)c * SS + t4);
    }
    for (int i = tid; i < 96; i += NTHREADS) {
        int p = i >> 4, t4 = (i & 15) * 4;
        *(float4*)(pol + p * 64 + t4) = *(const float4*)(pg + (size_t)p * SS + t4);
    }
    __syncthreads();

    // ---- x_with_polar = x + polar @ Wp + bp (A in place) ----
    #pragma unroll
    for (int idx = tid; idx < 2048; idx += NTHREADS) {
        int c = idx >> 4, t4 = (idx & 15) * 4;
        float4 v = *(const float4*)(A + c * ASTR + t4);
        #pragma unroll
        for (int p = 0; p < PCH; ++p) {
            float w = Wp[p * 128 + c];
            float4 pv = *(const float4*)(pol + p * 64 + t4);
            v.x = fmaf(pv.x, w, v.x); v.y = fmaf(pv.y, w, v.y);
            v.z = fmaf(pv.z, w, v.z); v.w = fmaf(pv.w, w, v.w);
        }
        float bb = bpv[c];
        v.x += bb; v.y += bb; v.z += bb; v.w += bb;
        *(float4*)(A + c * ASTR + t4) = v;
    }
    __syncthreads();

    // ---- LN1 -> X16 ----
    lnA(A, X16, g1, be1, red, tid);
    __syncthreads();

    // ---- Q+K fused (pipelined), V single ----
    {
        float accw[2][8][4];
        ZACC8(accw);
        gemm2(g_wfrag, g_wfrag + 8192, X16, accw, tid);
        epi16w(accw, 0, Q16, bq, false, tid);
        epi16w(accw, 4, K16, bk, false, tid);
    }
    {
        float acc[2][4][4];
        ZACC(acc);
        gemm_f(g_wfrag + 16384, X16, acc, tid);
        epi16n(acc, V16, bv, tid);
    }
    __syncthreads();

    // ---- per-token cross-head attention: 4 thr/token, 2 heads each (R12 form) ----
    {
        const int t = tid >> 2;
        const int h0q = (tid & 3) * 2;
        const uint4* Qv = (const uint4*)(Q16 + t * STRA);
        const uint4* Kv = (const uint4*)(K16 + t * STRA);
        const uint4* Vv = (const uint4*)(V16 + t * STRA);

        float q[2][16];
        up8(q[0],     Qv[h0q * 2]);
        up8(q[0] + 8, Qv[h0q * 2 + 1]);
        up8(q[1],     Qv[h0q * 2 + 2]);
        up8(q[1] + 8, Qv[h0q * 2 + 3]);

        float sc[2][NHEAD];
        #pragma unroll
        for (int g = 0; g < NHEAD; ++g) {
            float kv[16];
            up8(kv,     Kv[g * 2]);
            up8(kv + 8, Kv[g * 2 + 1]);
            #pragma unroll
            for (int hh = 0; hh < 2; ++hh) {
                float s = 0.f;
                #pragma unroll
                for (int i = 0; i < 16; ++i) s = fmaf(q[hh][i], kv[i], s);
                sc[hh][g] = s * 0.25f;
            }
        }
        #pragma unroll
        for (int hh = 0; hh < 2; ++hh) {
            float mx = sc[hh][0];
            #pragma unroll
            for (int g = 1; g < NHEAD; ++g) mx = fmaxf(mx, sc[hh][g]);
            float sum = 0.f;
            #pragma unroll
            for (int g = 0; g < NHEAD; ++g) { float e = __expf(sc[hh][g] - mx); sc[hh][g] = e; sum += e; }
            float inv = 1.f / sum;
            #pragma unroll
            for (int g = 0; g < NHEAD; ++g) sc[hh][g] *= inv;
        }
        float att[2][16];
        #pragma unroll
        for (int hh = 0; hh < 2; ++hh)
            #pragma unroll
            for (int i = 0; i < 16; ++i) att[hh][i] = 0.f;
        #pragma unroll
        for (int g = 0; g < NHEAD; ++g) {
            float vv[16];
            up8(vv,     Vv[g * 2]);
            up8(vv + 8, Vv[g * 2 + 1]);
            #pragma unroll
            for (int hh = 0; hh < 2; ++hh) {
                float w = sc[hh][g];
                #pragma unroll
                for (int i = 0; i < 16; ++i)
                    att[hh][i] = fmaf(w, vv[i], att[hh][i]);
            }
        }
        uint4* Xo = (uint4*)(X16 + t * STRA);
        #pragma unroll
        for (int hh = 0; hh < 2; ++hh) {
            uint4 w0, w1;
            w0.x = pk(att[hh][0],  att[hh][1]);  w0.y = pk(att[hh][2],  att[hh][3]);
            w0.z = pk(att[hh][4],  att[hh][5]);  w0.w = pk(att[hh][6],  att[hh][7]);
            w1.x = pk(att[hh][8],  att[hh][9]);  w1.y = pk(att[hh][10], att[hh][11]);
            w1.z = pk(att[hh][12], att[hh][13]); w1.w = pk(att[hh][14], att[hh][15]);
            Xo[(h0q + hh) * 2]     = w0;
            Xo[(h0q + hh) * 2 + 1] = w1;
        }
    }
    __syncthreads();

    // ---- out1 = attended @ Wo + bo + residual1 (A RMW) ----
    {
        float acc[2][4][4];
        ZACC(acc);
        gemm_f(g_wfrag + 24576, X16, acc, tid);
        epi32A(acc, A, bo, tid);
    }
    __syncthreads();

    // ---- LN2 -> X16 ----
    lnA(A, X16, g2, be2, red, tid);
    __syncthreads();

    // ---- FFN: two pair-phases; F1 pair fused (pipelined), F2 pair accumulated ----
    #pragma unroll 1
    for (int pr = 0; pr < 2; ++pr) {
        {
            float accw[2][8][4];
            ZACC8(accw);
            gemm2(g_wfrag + (4 + 2 * pr) * 8192, g_wfrag + (5 + 2 * pr) * 8192,
                  X16, accw, tid);
            epi16w(accw, 0, X2A, bf1 + (2 * pr) * 128,     true, tid);
            epi16w(accw, 4, X2B, bf1 + (2 * pr + 1) * 128, true, tid);
        }
        __syncthreads();
        {
            float acc2[2][4][4];
            ZACC(acc2);
            gemm_f(g_wfrag + (8 + 2 * pr) * 8192, X2A, acc2, tid);
            gemm_f(g_wfrag + (9 + 2 * pr) * 8192, X2B, acc2, tid);
            epi32A(acc2, A, pr == 0 ? bf2 : nullptr, tid);
        }
        __syncthreads();
    }

    // ---- coalesced global store ----
    float* og = out + (size_t)(b * CC) * SS + s0;
    #pragma unroll
    for (int idx = tid; idx < 2048; idx += NTHREADS) {
        int c = idx >> 4, t4 = (idx & 15) * 4;
        *(float4*)(og + (size_t)c * SS + t4) = *(const float4*)(A + c * ASTR + t4);
    }
}

extern "C" void kernel_launch(void* const* d_in, const int* in_sizes, int n_in,
                              void* d_out, int out_size)
{
    (void)in_sizes; (void)n_in; (void)out_size;
    cudaFuncSetAttribute(polar_attention_kernel,
                         cudaFuncAttributeMaxDynamicSharedMemorySize, SMEM_BYTES);

    const float* x     = (const float*)d_in[0];
    const float* polar = (const float*)d_in[1];
    const float* Wq    = (const float*)d_in[2];
    const float* bq    = (const float*)d_in[3];
    const float* Wk    = (const float*)d_in[4];
    const float* bk    = (const float*)d_in[5];
    const float* Wv    = (const float*)d_in[6];
    const float* bv    = (const float*)d_in[7];
    const float* Wp    = (const float*)d_in[8];
    const float* bp    = (const float*)d_in[9];
    const float* Wo    = (const float*)d_in[10];
    const float* bo    = (const float*)d_in[11];
    const float* g1    = (const float*)d_in[12];
    const float* be1   = (const float*)d_in[13];
    const float* g2    = (const float*)d_in[14];
    const float* be2   = (const float*)d_in[15];
    const float* W1    = (const float*)d_in[16];
    const float* bf1   = (const float*)d_in[17];
    const float* W2    = (const float*)d_in[18];
    const float* bf2   = (const float*)d_in[19];
    float* out = (float*)d_out;

    convert_weights<<<384, NTHREADS>>>(Wq, Wk, Wv, Wo, W1, W2);

    dim3 grid(NTOK / TOK);   // 4096 CTAs
    polar_attention_kernel<<<grid, NTHREADS, SMEM_BYTES>>>(
        x, polar, bq, bk, bv, Wp, bp, bo, g1, be1, g2, be2, bf1, bf2, out);
}

// round 17
// speedup vs baseline: 1.0271x; 1.0271x over previous
#include <cuda_runtime.h>
#include <cuda_fp16.h>

#define CC   128
#define PCH  6
#define SS   131072
#define NTOK 262144
#define TOK  64
#define NTHREADS 256
#define NHEAD 8

#define STRA 68      // fp16 activation row stride (u32 words)
#define ASTR 68      // fp32 residual A column stride: A[c][t]

// ---- shared memory layout (32-bit word offsets) ----
#define OFF_A    0                       // fp32 A [128][68] col-major
#define OFF_X    (128*ASTR)              // 8704
#define OFF_Q    (OFF_X + 64*STRA)       // 13056
#define OFF_K    (OFF_Q + 64*STRA)       // 17408
#define OFF_V    (OFF_K + 64*STRA)       // 21760
#define OFF_X2A  OFF_Q                   // FFN relu buf A (Q dead in FFN)
#define OFF_X2B  OFF_K                   // FFN relu buf B (K dead in FFN)
#define OFF_POL  (OFF_V + 64*STRA)       // 26112
#define OFF_RED  (OFF_POL + PCH*64)      // 26496: LN reduction scratch
#define SMEM_WORDS (OFF_RED + 512)       // 27008
#define SMEM_BYTES (SMEM_WORDS*4)        // 108032 B -> 2 CTAs/SM

// 12 fragment blocks of 128x128: Wq,Wk,Wv,Wo, W1 n-chunks x4, W2 k-chunks x4
__device__ unsigned g_wfrag[12 * 8192];

// ---- fp16 helpers ----
__device__ __forceinline__ unsigned pk(float lo, float hi) {
    __half2 h = __floats2half2_rn(lo, hi);
    return *reinterpret_cast<unsigned*>(&h);
}
__device__ __forceinline__ float2 up(unsigned w) {
    __half2 h = *reinterpret_cast<__half2*>(&w);
    return __half22float2(h);
}
__device__ __forceinline__ void up8(float* f, uint4 u) {
    float2 a = up(u.x), b = up(u.y), c = up(u.z), d = up(u.w);
    f[0] = a.x; f[1] = a.y; f[2] = b.x; f[3] = b.y;
    f[4] = c.x; f[5] = c.y; f[6] = d.x; f[7] = d.y;
}
__device__ __forceinline__ void mma16(float (&d)[4],
    unsigned a0, unsigned a1, unsigned a2, unsigned a3, unsigned b0, unsigned b1)
{
    asm("mma.sync.aligned.m16n8k16.row.col.f32.f16.f16.f32 "
        "{%0,%1,%2,%3}, {%4,%5,%6,%7}, {%8,%9}, {%0,%1,%2,%3};"
        : "+f"(d[0]), "+f"(d[1]), "+f"(d[2]), "+f"(d[3])
        : "r"(a0), "r"(a1), "r"(a2), "r"(a3), "r"(b0), "r"(b1));
}
__device__ __forceinline__ void ldsm4(unsigned (&a)[4], unsigned addr) {
    asm volatile("ldmatrix.sync.aligned.m8n8.x4.shared.b16 {%0,%1,%2,%3}, [%4];"
        : "=r"(a[0]), "=r"(a[1]), "=r"(a[2]), "=r"(a[3]) : "r"(addr));
}

// ---- weight conversion kernel: fp32 row-major -> fp16 fragment-major ----
__global__ void convert_weights(const float* __restrict__ Wq, const float* __restrict__ Wk,
                                const float* __restrict__ Wv, const float* __restrict__ Wo,
                                const float* __restrict__ W1, const float* __restrict__ W2)
{
    int gid = blockIdx.x * blockDim.x + threadIdx.x;
    int blk = gid >> 13;
    int w   = gid & 8191;
    int q4   = w & 3;
    int lane = (w >> 2) & 31;
    int h    = (w >> 7) & 1;
    int nw   = (w >> 8) & 3;
    int ks   = w >> 10;
    int j    = q4 & 1;
    int nt   = h * 2 + (q4 >> 1);
    int qd = lane >> 2, tg = lane & 3;
    int k = ks * 16 + tg * 2 + j * 8;
    int n = nw * 32 + nt * 8 + qd;

    const float* W; int ld = 128, k0 = 0, n0 = 0;
    if      (blk == 0) W = Wq;
    else if (blk == 1) W = Wk;
    else if (blk == 2) W = Wv;
    else if (blk == 3) W = Wo;
    else if (blk < 8)  { W = W1; ld = 512; n0 = (blk - 4) * 128; }
    else               { W = W2; k0 = (blk - 8) * 128; }

    const float* p = W + (size_t)(k0 + k) * ld + n0 + n;
    g_wfrag[gid] = pk(p[0], p[ld]);
}

// ---- depth-4 B pipeline: P[2s],P[2s+1] hold stage (ks+s), s=0..3 ----
__device__ __forceinline__ void bpinit(uint4 (&P)[8], const unsigned* __restrict__ Wf, int tid) {
    const uint4* bp = (const uint4*)Wf + (tid >> 6) * 64 + (tid & 31);
    #pragma unroll
    for (int s = 0; s < 4; ++s) {
        P[2 * s]     = bp[s * 256];
        P[2 * s + 1] = bp[s * 256 + 32];
    }
}

// ---- GEMM: acc[2][4][4] += X[64x128 fp16] @ Wf; A pipelined 1-ahead,
//      B pipelined 4-ahead; tail streams Wfn stages 0..3 when chain ----
__device__ __forceinline__ void gemm_pf(
    const unsigned* __restrict__ Wf, const unsigned* __restrict__ Wfn,
    const unsigned* __restrict__ Xs,
    float (&acc)[2][4][4], int tid, uint4 (&P)[8], bool chain)
{
    const int lane = tid & 31, wid = tid >> 5;
    const int mw = wid & 1, nw = wid >> 1;

    unsigned abase;
    {
        const unsigned* p = Xs + (mw * 32 + (lane & 15)) * STRA;
        abase = (unsigned)__cvta_generic_to_shared(p) + ((lane >> 4) << 4);
    }
    const uint4* bp  = (const uint4*)Wf  + nw * 64 + lane;
    const uint4* bpn = (const uint4*)Wfn + nw * 64 + lane;

    unsigned aC[2][4], aN[2][4];
    ldsm4(aC[0], abase);
    ldsm4(aC[1], abase + 16 * STRA * 4);

    #pragma unroll
    for (int ks = 0; ks < 8; ++ks) {
        // fetch stage ks+4 (this W) or next GEMM's stage ks-4
        uint4 f0 = P[6], f1 = P[7];
        if (ks < 4)      { f0 = bp[(ks + 4) * 256];  f1 = bp[(ks + 4) * 256 + 32]; }
        else if (chain)  { f0 = bpn[(ks - 4) * 256]; f1 = bpn[(ks - 4) * 256 + 32]; }
        if (ks < 7) {
            unsigned an = abase + (ks + 1) * 32;
            ldsm4(aN[0], an);
            ldsm4(aN[1], an + 16 * STRA * 4);
        }
        #pragma unroll
        for (int mm = 0; mm < 2; ++mm) {
            mma16(acc[mm][0], aC[mm][0], aC[mm][1], aC[mm][2], aC[mm][3], P[0].x, P[0].y);
            mma16(acc[mm][1], aC[mm][0], aC[mm][1], aC[mm][2], aC[mm][3], P[0].z, P[0].w);
            mma16(acc[mm][2], aC[mm][0], aC[mm][1], aC[mm][2], aC[mm][3], P[1].x, P[1].y);
            mma16(acc[mm][3], aC[mm][0], aC[mm][1], aC[mm][2], aC[mm][3], P[1].z, P[1].w);
        }
        #pragma unroll
        for (int s = 0; s < 6; ++s) P[s] = P[s + 2];
        P[6] = f0; P[7] = f1;
        #pragma unroll
        for (int mm = 0; mm < 2; ++mm)
            #pragma unroll
            for (int r = 0; r < 4; ++r) aC[mm][r] = aN[mm][r];
    }
}

// epilogue -> fp16 activation buffer (+bias from gmem, optional relu)
__device__ __forceinline__ void epi16(float (&acc)[2][4][4], unsigned* __restrict__ dst,
                                      const float* __restrict__ bias, bool relu, int tid)
{
    const int lane = tid & 31, wid = tid >> 5;
    const int mw = wid & 1, nw = wid >> 1;
    const int qd = lane >> 2, tg = lane & 3;
    #pragma unroll
    for (int nt = 0; nt < 4; ++nt) {
        const int cb = nw * 32 + nt * 8 + tg * 2;
        float2 b = *(const float2*)(bias + cb);
        #pragma unroll
        for (int mm = 0; mm < 2; ++mm) {
            const int r0 = mw * 32 + mm * 16 + qd;
            float v0 = acc[mm][nt][0] + b.x, v1 = acc[mm][nt][1] + b.y;
            float v2 = acc[mm][nt][2] + b.x, v3 = acc[mm][nt][3] + b.y;
            if (relu) {
                v0 = fmaxf(v0, 0.f); v1 = fmaxf(v1, 0.f);
                v2 = fmaxf(v2, 0.f); v3 = fmaxf(v3, 0.f);
            }
            dst[r0 * STRA + (cb >> 1)]       = pk(v0, v1);
            dst[(r0 + 8) * STRA + (cb >> 1)] = pk(v2, v3);
        }
    }
}

// epilogue -> fp32 A (col-major) RMW: A[c][t] += acc (+bias if non-null)
__device__ __forceinline__ void epi32A(float (&acc)[2][4][4], float* __restrict__ A,
                                       const float* __restrict__ bias, int tid)
{
    const int lane = tid & 31, wid = tid >> 5;
    const int mw = wid & 1, nw = wid >> 1;
    const int qd = lane >> 2, tg = lane & 3;
    #pragma unroll
    for (int nt = 0; nt < 4; ++nt) {
        const int cb = nw * 32 + nt * 8 + tg * 2;
        float bx = 0.f, by = 0.f;
        if (bias) { float2 b = *(const float2*)(bias + cb); bx = b.x; by = b.y; }
        #pragma unroll
        for (int mm = 0; mm < 2; ++mm) {
            const int r0 = mw * 32 + mm * 16 + qd;
            A[cb * ASTR + r0]           += acc[mm][nt][0] + bx;
            A[(cb + 1) * ASTR + r0]     += acc[mm][nt][1] + by;
            A[cb * ASTR + r0 + 8]       += acc[mm][nt][2] + bx;
            A[(cb + 1) * ASTR + r0 + 8] += acc[mm][nt][3] + by;
        }
    }
}

// LayerNorm: conflict-free mapping t=tid&63, q=tid>>6; smem 2-stage reduce.
__device__ __forceinline__ void lnA(const float* __restrict__ A, unsigned* __restrict__ X,
                                    const float* __restrict__ g, const float* __restrict__ be,
                                    float* __restrict__ red, int tid)
{
    const int t = tid & 63, q = tid >> 6;
    const float* Ac = A + q * 32 * ASTR + t;
    float v[32];
    float s = 0.f, sq = 0.f;
    #pragma unroll
    for (int i = 0; i < 32; ++i) {
        v[i] = Ac[i * ASTR];
        s += v[i]; sq += v[i] * v[i];
    }
    red[q * 64 + t]       = s;
    red[256 + q * 64 + t] = sq;
    __syncthreads();
    float S = 0.f, SQ = 0.f;
    #pragma unroll
    for (int k = 0; k < 4; ++k) {
        S  += red[k * 64 + t];
        SQ += red[256 + k * 64 + t];
    }
    float m = S * (1.f / CC);
    float rs = rsqrtf(SQ * (1.f / CC) - m * m + 1e-5f);

    const float2* g2 = (const float2*)(g + q * 32);
    const float2* b2 = (const float2*)(be + q * 32);
    uint4* o = (uint4*)(X + t * STRA + q * 16);
    #pragma unroll
    for (int c4 = 0; c4 < 4; ++c4) {
        uint4 w;
        unsigned r[4];
        #pragma unroll
        for (int k = 0; k < 4; ++k) {
            int i = c4 * 4 + k;
            float2 gg = g2[i], bb = b2[i];
            r[k] = pk((v[2*i] - m) * rs * gg.x + bb.x,
                      (v[2*i+1] - m) * rs * gg.y + bb.y);
        }
        w.x = r[0]; w.y = r[1]; w.z = r[2]; w.w = r[3];
        o[c4] = w;
    }
}

#define ZACC(a) { _Pragma("unroll") for (int _m = 0; _m < 2; ++_m) _Pragma("unroll") for (int _n = 0; _n < 4; ++_n) { a[_m][_n][0]=0.f; a[_m][_n][1]=0.f; a[_m][_n][2]=0.f; a[_m][_n][3]=0.f; } }

__global__ void __launch_bounds__(NTHREADS, 2)
polar_attention_kernel(
    const float* __restrict__ x,   const float* __restrict__ polar,
    const float* __restrict__ bq,  const float* __restrict__ bk,
    const float* __restrict__ bv,  const float* __restrict__ Wp,
    const float* __restrict__ bpv, const float* __restrict__ bo,
    const float* __restrict__ g1,  const float* __restrict__ be1,
    const float* __restrict__ g2,  const float* __restrict__ be2,
    const float* __restrict__ bf1, const float* __restrict__ bf2,
    float* __restrict__ out)
{
    extern __shared__ float sm[];
    unsigned* smu = (unsigned*)sm;
    float*    A   = sm + OFF_A;
    unsigned* X16 = smu + OFF_X;
    unsigned* Q16 = smu + OFF_Q;
    unsigned* K16 = smu + OFF_K;
    unsigned* V16 = smu + OFF_V;
    float*    pol = sm + OFF_POL;
    float*    red = sm + OFF_RED;

    const int tid = threadIdx.x;
    const int n0  = blockIdx.x * TOK;
    const int b   = n0 / SS;
    const int s0  = n0 % SS;

    const float* xg = x + (size_t)(b * CC) * SS + s0;
    const float* pg = polar + (size_t)(b * PCH) * SS + s0;

    // prime the B pipeline for Wq immediately (hidden under tile load + LN1)
    uint4 P[8];
    bpinit(P, g_wfrag, tid);

    // ---- load x tile (col-major A) + polar ----
    #pragma unroll
    for (int idx = tid; idx < 2048; idx += NTHREADS) {
        int c = idx >> 4, t4 = (idx & 15) * 4;
        *(float4*)(A + c * ASTR + t4) = *(const float4*)(xg + (size_t)c * SS + t4);
    }
    for (int i = tid; i < 96; i += NTHREADS) {
        int p = i >> 4, t4 = (i & 15) * 4;
        *(float4*)(pol + p * 64 + t4) = *(const float4*)(pg + (size_t)p * SS + t4);
    }
    __syncthreads();

    // ---- x_with_polar = x + polar @ Wp + bp (A in place) ----
    #pragma unroll
    for (int idx = tid; idx < 2048; idx += NTHREADS) {
        int c = idx >> 4, t4 = (idx & 15) * 4;
        float4 v = *(const float4*)(A + c * ASTR + t4);
        #pragma unroll
        for (int p = 0; p < PCH; ++p) {
            float w = Wp[p * 128 + c];
            float4 pv = *(const float4*)(pol + p * 64 + t4);
            v.x = fmaf(pv.x, w, v.x); v.y = fmaf(pv.y, w, v.y);
            v.z = fmaf(pv.z, w, v.z); v.w = fmaf(pv.w, w, v.w);
        }
        float bb = bpv[c];
        v.x += bb; v.y += bb; v.z += bb; v.w += bb;
        *(float4*)(A + c * ASTR + t4) = v;
    }
    __syncthreads();

    // ---- LN1 -> X16 ----
    lnA(A, X16, g1, be1, red, tid);
    __syncthreads();

    // ---- Q,K,V (chained depth-4 B pipeline) ----
    float acc[2][4][4];
    ZACC(acc); gemm_pf(g_wfrag,         g_wfrag + 8192,  X16, acc, tid, P, true);  epi16(acc, Q16, bq, false, tid);
    ZACC(acc); gemm_pf(g_wfrag + 8192,  g_wfrag + 16384, X16, acc, tid, P, true);  epi16(acc, K16, bk, false, tid);
    ZACC(acc); gemm_pf(g_wfrag + 16384, g_wfrag + 16384, X16, acc, tid, P, false); epi16(acc, V16, bv, false, tid);
    __syncthreads();

    // ---- per-token cross-head attention: 4 thr/token, 2 heads each ----
    {
        const int t = tid >> 2;
        const int h0q = (tid & 3) * 2;
        const uint4* Qv = (const uint4*)(Q16 + t * STRA);
        const uint4* Kv = (const uint4*)(K16 + t * STRA);
        const uint4* Vv = (const uint4*)(V16 + t * STRA);

        float q[2][16];
        up8(q[0],     Qv[h0q * 2]);
        up8(q[0] + 8, Qv[h0q * 2 + 1]);
        up8(q[1],     Qv[h0q * 2 + 2]);
        up8(q[1] + 8, Qv[h0q * 2 + 3]);

        float sc[2][NHEAD];
        #pragma unroll
        for (int g = 0; g < NHEAD; ++g) {
            float kv[16];
            up8(kv,     Kv[g * 2]);
            up8(kv + 8, Kv[g * 2 + 1]);
            #pragma unroll
            for (int hh = 0; hh < 2; ++hh) {
                float s = 0.f;
                #pragma unroll
                for (int i = 0; i < 16; ++i) s = fmaf(q[hh][i], kv[i], s);
                sc[hh][g] = s * 0.25f;
            }
        }
        #pragma unroll
        for (int hh = 0; hh < 2; ++hh) {
            float mx = sc[hh][0];
            #pragma unroll
            for (int g = 1; g < NHEAD; ++g) mx = fmaxf(mx, sc[hh][g]);
            float sum = 0.f;
            #pragma unroll
            for (int g = 0; g < NHEAD; ++g) { float e = __expf(sc[hh][g] - mx); sc[hh][g] = e; sum += e; }
            float inv = 1.f / sum;
            #pragma unroll
            for (int g = 0; g < NHEAD; ++g) sc[hh][g] *= inv;
        }
        float att[2][16];
        #pragma unroll
        for (int hh = 0; hh < 2; ++hh)
            #pragma unroll
            for (int i = 0; i < 16; ++i) att[hh][i] = 0.f;
        #pragma unroll
        for (int g = 0; g < NHEAD; ++g) {
            float vv[16];
            up8(vv,     Vv[g * 2]);
            up8(vv + 8, Vv[g * 2 + 1]);
            #pragma unroll
            for (int hh = 0; hh < 2; ++hh) {
                float w = sc[hh][g];
                #pragma unroll
                for (int i = 0; i < 16; ++i)
                    att[hh][i] = fmaf(w, vv[i], att[hh][i]);
            }
        }
        uint4* Xo = (uint4*)(X16 + t * STRA);
        #pragma unroll
        for (int hh = 0; hh < 2; ++hh) {
            uint4 w0, w1;
            w0.x = pk(att[hh][0],  att[hh][1]);  w0.y = pk(att[hh][2],  att[hh][3]);
            w0.z = pk(att[hh][4],  att[hh][5]);  w0.w = pk(att[hh][6],  att[hh][7]);
            w1.x = pk(att[hh][8],  att[hh][9]);  w1.y = pk(att[hh][10], att[hh][11]);
            w1.z = pk(att[hh][12], att[hh][13]); w1.w = pk(att[hh][14], att[hh][15]);
            Xo[(h0q + hh) * 2]     = w0;
            Xo[(h0q + hh) * 2 + 1] = w1;
        }
    }
    // re-prime B pipeline for Wo (overlaps the sync below)
    bpinit(P, g_wfrag + 24576, tid);
    __syncthreads();

    // ---- out1 = attended @ Wo + bo + residual1; tail prefetches W1[0] ----
    ZACC(acc); gemm_pf(g_wfrag + 24576, g_wfrag + 4 * 8192, X16, acc, tid, P, true);
    epi32A(acc, A, bo, tid);
    __syncthreads();

    // ---- LN2 -> X16 ----
    lnA(A, X16, g2, be2, red, tid);
    __syncthreads();

    // ---- FFN: acc2 held; relu double-buffered; B chained through all 8 GEMMs ----
    float acc2[2][4][4];
    ZACC(acc2);
    #pragma unroll 1
    for (int jb = 0; jb < 4; ++jb) {
        unsigned* X2 = smu + ((jb & 1) ? OFF_X2B : OFF_X2A);
        float h1[2][4][4];
        ZACC(h1);
        gemm_pf(g_wfrag + (4 + jb) * 8192, g_wfrag + (8 + jb) * 8192, X16, h1, tid, P, true);
        epi16(h1, X2, bf1 + jb * 128, true, tid);
        __syncthreads();
        bool last = (jb == 3);
        const unsigned* nxt = last ? g_wfrag : g_wfrag + (5 + jb) * 8192;
        gemm_pf(g_wfrag + (8 + jb) * 8192, nxt, X2, acc2, tid, P, !last);
    }
    __syncthreads();
    epi32A(acc2, A, bf2, tid);
    __syncthreads();

    // ---- coalesced global store ----
    float* og = out + (size_t)(b * CC) * SS + s0;
    #pragma unroll
    for (int idx = tid; idx < 2048; idx += NTHREADS) {
        int c = idx >> 4, t4 = (idx & 15) * 4;
        *(float4*)(og + (size_t)c * SS + t4) = *(const float4*)(A + c * ASTR + t4);
    }
}

extern "C" void kernel_launch(void* const* d_in, const int* in_sizes, int n_in,
                              void* d_out, int out_size)
{
    (void)in_sizes; (void)n_in; (void)out_size;
    cudaFuncSetAttribute(polar_attention_kernel,
                         cudaFuncAttributeMaxDynamicSharedMemorySize, SMEM_BYTES);

    const float* x     = (const float*)d_in[0];
    const float* polar = (const float*)d_in[1];
    const float* Wq    = (const float*)d_in[2];
    const float* bq    = (const float*)d_in[3];
    const float* Wk    = (const float*)d_in[4];
    const float* bk    = (const float*)d_in[5];
    const float* Wv    = (const float*)d_in[6];
    const float* bv    = (const float*)d_in[7];
    const float* Wp    = (const float*)d_in[8];
    const float* bp    = (const float*)d_in[9];
    const float* Wo    = (const float*)d_in[10];
    const float* bo    = (const float*)d_in[11];
    const float* g1    = (const float*)d_in[12];
    const float* be1   = (const float*)d_in[13];
    const float* g2    = (const float*)d_in[14];
    const float* be2   = (const float*)d_in[15];
    const float* W1    = (const float*)d_in[16];
    const float* bf1   = (const float*)d_in[17];
    const float* W2    = (const float*)d_in[18];
    const float* bf2   = (const float*)d_in[19];
    float* out = (float*)d_out;

    convert_weights<<<384, NTHREADS>>>(Wq, Wk, Wv, Wo, W1, W2);

    dim3 grid(NTOK / TOK);   // 4096 CTAs
    polar_attention_kernel<<<grid, NTHREADS, SMEM_BYTES>>>(
        x, polar, bq, bk, bv, Wp, bp, bo, g1, be1, g2, be2, bf1, bf2, out);
}